// round 4
// baseline (speedup 1.0000x reference)
#include <cuda_runtime.h>

#define B_N   32768
#define FIN   64
#define HID   32
#define E_N   25
#define HG    96
#define BAND_HG 8
#define NBAND 12
#define MB    224      // 8 heads * 28 (25 padded to 28: f32x2 pairs + 16B-aligned head base)
#define EPD_STRIDE 65  // u64 row stride for e-tile
#define NT    8        // row-tiles per kernC block

typedef unsigned long long u64;

// scratch (static device globals — no allocation)
__device__ float g_h2[B_N * HID];          // 4 MB intermediate
__device__ float g_part[1024][2 * HID];    // per-block BN partial sums
__device__ float g_scale[HID];
__device__ float g_shift[HID];

__device__ __forceinline__ float selu_f(float x) {
    float p = 1.0507009873554805f * x;
    float n = 1.7580993408473766f * (__expf(x) - 1.0f);  // lambda*alpha
    return x > 0.0f ? p : n;
}
__device__ __forceinline__ u64 pk2(float lo, float hi) {
    u64 r;
    asm("mov.b64 %0, {%1,%2};" : "=l"(r)
        : "r"(__float_as_uint(lo)), "r"(__float_as_uint(hi)));
    return r;
}
__device__ __forceinline__ void upk2(u64 v, float& lo, float& hi) {
    unsigned int a, b;
    asm("mov.b64 {%0,%1}, %2;" : "=r"(a), "=r"(b) : "l"(v));
    lo = __uint_as_float(a); hi = __uint_as_float(b);
}
// packed fp32x2 FMA (FFMA2) — only reachable via PTX
#define FFMA2(d, a, b) asm("fma.rn.f32x2 %0, %1, %2, %0;" : "+l"(d) : "l"(a), "l"(b))

// ---------------------------------------------------------------------------
// Kernel A: h = selu(X@W1+b1); h2 = h@W2+b2; store h2 + deterministic BN partials
// grid 1024 x 128 threads; 32 rows/block; 4 threads per row (8 outputs each)
// smem: xs[32][68] | w1s[64][32] | w2s[32][32] | b1s,b2s | hs[32][36]
// ---------------------------------------------------------------------------
__global__ void __launch_bounds__(128, 8) kernA(
    const float* __restrict__ X,
    const float* __restrict__ W1, const float* __restrict__ b1,
    const float* __restrict__ W2, const float* __restrict__ b2)
{
    extern __shared__ char sm[];
    float* xs  = (float*)sm;                          // 32*68*4 = 8704 B
    float* w1s = (float*)(sm + 8704);                 // 8192 B
    float* w2s = (float*)(sm + 8704 + 8192);          // 4096 B
    float* b1s = (float*)(sm + 8704 + 8192 + 4096);   // 128 B
    float* b2s = b1s + HID;                           // 128 B
    float* hs  = (float*)(sm + 8704 + 8192 + 4096 + 256); // 32*36*4 = 4608 B

    int t = threadIdx.x;
    int rowbase = blockIdx.x * 32;
    const float* Xb = X + (size_t)rowbase * FIN;

    // coalesced float4 stage-in
    #pragma unroll
    for (int j = 0; j < 4; j++) {               // 512 float4 = 2048 floats
        int idx = t + j * 128;
        float4 v = ((const float4*)Xb)[idx];
        int row = idx >> 4, col = (idx & 15) * 4;
        *(float4*)&xs[row * 68 + col] = v;
    }
    #pragma unroll
    for (int j = 0; j < 4; j++) ((float4*)w1s)[t + j * 128] = ((const float4*)W1)[t + j * 128];
    #pragma unroll
    for (int j = 0; j < 2; j++) ((float4*)w2s)[t + j * 128] = ((const float4*)W2)[t + j * 128];
    if (t < HID) { b1s[t] = b1[t]; b2s[t] = b2[t]; }
    __syncthreads();

    int r  = t >> 2;        // row 0..31
    int j0 = (t & 3) * 8;   // output col group

    // stage 1: 8 outputs per thread
    u64 acc[4];
    #pragma unroll
    for (int p = 0; p < 4; p++) acc[p] = *(const u64*)&b1s[j0 + 2 * p];
    #pragma unroll 8
    for (int k = 0; k < FIN; k++) {
        float xk = xs[r * 68 + k];
        u64 xv = pk2(xk, xk);
        ulonglong2 w0 = *(const ulonglong2*)&w1s[k * HID + j0];
        ulonglong2 w1v = *(const ulonglong2*)&w1s[k * HID + j0 + 4];
        FFMA2(acc[0], xv, w0.x);
        FFMA2(acc[1], xv, w0.y);
        FFMA2(acc[2], xv, w1v.x);
        FFMA2(acc[3], xv, w1v.y);
    }
    float hv[8];
    #pragma unroll
    for (int p = 0; p < 4; p++) {
        float a, b; upk2(acc[p], a, b);
        hv[2 * p] = selu_f(a); hv[2 * p + 1] = selu_f(b);
    }
    *(float4*)&hs[r * 36 + j0]     = make_float4(hv[0], hv[1], hv[2], hv[3]);
    *(float4*)&hs[r * 36 + j0 + 4] = make_float4(hv[4], hv[5], hv[6], hv[7]);
    __syncthreads();

    // stage 2
    u64 acc2[4];
    #pragma unroll
    for (int p = 0; p < 4; p++) acc2[p] = *(const u64*)&b2s[j0 + 2 * p];
    #pragma unroll 8
    for (int k = 0; k < HID; k++) {
        float hk = hs[r * 36 + k];
        u64 hvv = pk2(hk, hk);
        ulonglong2 w0 = *(const ulonglong2*)&w2s[k * HID + j0];
        ulonglong2 w1v = *(const ulonglong2*)&w2s[k * HID + j0 + 4];
        FFMA2(acc2[0], hvv, w0.x);
        FFMA2(acc2[1], hvv, w0.y);
        FFMA2(acc2[2], hvv, w1v.x);
        FFMA2(acc2[3], hvv, w1v.y);
    }
    float o[8];
    #pragma unroll
    for (int p = 0; p < 4; p++) upk2(acc2[p], o[2 * p], o[2 * p + 1]);

    // h2 out (coalesced float4)
    float* H2r = g_h2 + (size_t)(rowbase + r) * HID + j0;
    *(float4*)H2r       = make_float4(o[0], o[1], o[2], o[3]);
    *(float4*)(H2r + 4) = make_float4(o[4], o[5], o[6], o[7]);

    __syncthreads();   // hs reads done; reuse for h2
    *(float4*)&hs[r * 36 + j0]     = make_float4(o[0], o[1], o[2], o[3]);
    *(float4*)&hs[r * 36 + j0 + 4] = make_float4(o[4], o[5], o[6], o[7]);
    __syncthreads();

    if (t < HID) {
        float s = 0.f, s2 = 0.f;
        #pragma unroll 8
        for (int rr = 0; rr < 32; rr++) {
            float v = hs[rr * 36 + t];
            s += v; s2 += v * v;
        }
        g_part[blockIdx.x][t]       = s;
        g_part[blockIdx.x][HID + t] = s2;
    }
}

// ---------------------------------------------------------------------------
// Kernel B: fold 1024 partials -> scale/shift (deterministic)
// 256 threads: col = t&31, chunk = t>>5 (8 chunks x 128 blocks)
// ---------------------------------------------------------------------------
__global__ void kernB(const float* __restrict__ gamma, const float* __restrict__ beta) {
    __shared__ float ps[8][64];
    int t = threadIdx.x;
    int c = t & 31, ch = t >> 5;
    float s = 0.f, s2 = 0.f;
    #pragma unroll 4
    for (int b = ch * 128; b < ch * 128 + 128; b++) {
        s  += g_part[b][c];
        s2 += g_part[b][HID + c];
    }
    ps[ch][c] = s; ps[ch][HID + c] = s2;
    __syncthreads();
    if (t < HID) {
        float S = 0.f, S2 = 0.f;
        #pragma unroll
        for (int ch2 = 0; ch2 < 8; ch2++) { S += ps[ch2][t]; S2 += ps[ch2][HID + t]; }
        float mu  = S  * (1.0f / B_N);
        float var = S2 * (1.0f / B_N) - mu * mu;
        float sc  = gamma[t] * rsqrtf(var + 1e-5f);
        g_scale[t] = sc;
        g_shift[t] = beta[t] - mu * sc;
    }
}

// ---------------------------------------------------------------------------
// Kernel C: e = selu(BN(h2)); D = e @ Wh (+bh in acc init); selu; L1-norm; write
// grid (12 bands, 64) x 256 threads; each block processes NT=8 tiles of 64 rows
// smem: bhs[224] | wch[32][224] | sss[64] | epd[32][65] u64   (weights persist)
// thread: 2 rows x 13 m-pairs (one head) -> 26 f32x2 accumulators
// ---------------------------------------------------------------------------
__global__ void __launch_bounds__(256, 3) kernC(
    const float* __restrict__ Wh, const float* __restrict__ bh,
    float* __restrict__ out)
{
    extern __shared__ char sm[];
    float* bhs = (float*)sm;                               // 896 B
    float* wch = (float*)(sm + 896);                       // 32*224*4 = 28672 B
    float* sss = (float*)(sm + 896 + 28672);               // 256 B (scale|shift)
    u64*   epd = (u64*)(sm + 896 + 28672 + 256);           // 32*65*8 = 16640 B

    int t = threadIdx.x;
    int band = blockIdx.x;

    // biases (pad cols 25..27 -> 0)
    for (int i = t; i < BAND_HG * 28; i += 256) {
        int hgl = i / 28, j = i - hgl * 28;
        bhs[i] = (j < E_N) ? bh[(band * BAND_HG + hgl) * E_N + j] : 0.0f;
    }
    // weights: Wh[hg][k][j] -> wch[k][hgl*28 + j]; zero pad col 25 (26,27 never read)
    for (int i = t; i < BAND_HG * HID * E_N; i += 256) {
        int hgl = i / (HID * E_N);
        int rem = i - hgl * HID * E_N;
        int k = rem / E_N, j = rem - k * E_N;
        wch[k * MB + hgl * 28 + j] = Wh[(size_t)(band * BAND_HG + hgl) * HID * E_N + rem];
    }
    if (t < HID * BAND_HG) {
        int k = t >> 3, hgl = t & 7;
        wch[k * MB + hgl * 28 + 25] = 0.0f;
    }
    if (t < HID) { sss[t] = g_scale[t]; sss[HID + t] = g_shift[t]; }

    int tx = t & 31;        // row lane
    int my = t >> 5;        // head within band (warp-uniform)
    int wb = my * 28;
    int r8 = t >> 2;        // e-tile row for this thread's 8 h2 elements
    int k0 = (t & 3) * 8;   // e-tile k-group

    int row0 = blockIdx.y * (NT * 64);
    // first tile prefetch (8 h2 elements/thread)
    const float* h2p = g_h2 + (size_t)row0 * HID;
    float4 pf0 = ((const float4*)h2p)[t * 2];
    float4 pf1 = ((const float4*)h2p)[t * 2 + 1];

    for (int tile = 0; tile < NT; tile++) {
        __syncthreads();   // weights/sss ready (tile 0) / epd reads of prev tile done
        // epd store: BN + selu, duplicated f32x2, layout [k][row]
        {
            float vv[8] = {pf0.x, pf0.y, pf0.z, pf0.w, pf1.x, pf1.y, pf1.z, pf1.w};
            #pragma unroll
            for (int u = 0; u < 8; u++) {
                float v = fmaf(vv[u], sss[k0 + u], sss[HID + k0 + u]);
                v = selu_f(v);
                epd[(k0 + u) * EPD_STRIDE + r8] = pk2(v, v);
            }
        }
        __syncthreads();

        // prefetch next tile
        if (tile < NT - 1) {
            const float* nxt = g_h2 + (size_t)(row0 + 64) * HID;
            pf0 = ((const float4*)nxt)[t * 2];
            pf1 = ((const float4*)nxt)[t * 2 + 1];
        }

        // mainloop: acc init = bias (added once per output)
        u64 acc[2][13];
        #pragma unroll
        for (int p = 0; p < 13; p++) {
            u64 bp = *(const u64*)&bhs[wb + 2 * p];
            acc[0][p] = bp; acc[1][p] = bp;
        }
        #pragma unroll 4
        for (int k = 0; k < HID; k++) {
            u64 e0 = epd[k * EPD_STRIDE + tx];
            u64 e1 = epd[k * EPD_STRIDE + tx + 32];
            const float* wr = &wch[k * MB + wb];
            ulonglong2 wA = *(const ulonglong2*)(wr);
            ulonglong2 wB = *(const ulonglong2*)(wr + 4);
            ulonglong2 wC = *(const ulonglong2*)(wr + 8);
            ulonglong2 wD = *(const ulonglong2*)(wr + 12);
            ulonglong2 wE = *(const ulonglong2*)(wr + 16);
            ulonglong2 wF = *(const ulonglong2*)(wr + 20);
            u64 wG = *(const u64*)(wr + 24);
            FFMA2(acc[0][0], e0, wA.x);  FFMA2(acc[1][0], e1, wA.x);
            FFMA2(acc[0][1], e0, wA.y);  FFMA2(acc[1][1], e1, wA.y);
            FFMA2(acc[0][2], e0, wB.x);  FFMA2(acc[1][2], e1, wB.x);
            FFMA2(acc[0][3], e0, wB.y);  FFMA2(acc[1][3], e1, wB.y);
            FFMA2(acc[0][4], e0, wC.x);  FFMA2(acc[1][4], e1, wC.x);
            FFMA2(acc[0][5], e0, wC.y);  FFMA2(acc[1][5], e1, wC.y);
            FFMA2(acc[0][6], e0, wD.x);  FFMA2(acc[1][6], e1, wD.x);
            FFMA2(acc[0][7], e0, wD.y);  FFMA2(acc[1][7], e1, wD.y);
            FFMA2(acc[0][8], e0, wE.x);  FFMA2(acc[1][8], e1, wE.x);
            FFMA2(acc[0][9], e0, wE.y);  FFMA2(acc[1][9], e1, wE.y);
            FFMA2(acc[0][10], e0, wF.x); FFMA2(acc[1][10], e1, wF.x);
            FFMA2(acc[0][11], e0, wF.y); FFMA2(acc[1][11], e1, wF.y);
            FFMA2(acc[0][12], e0, wG);   FFMA2(acc[1][12], e1, wG);
        }

        // epilogue: selu + L1-normalize + direct stores (sign(d)*|d|/l1 == d/l1)
        #pragma unroll
        for (int ri = 0; ri < 2; ri++) {
            float v[26];
            #pragma unroll
            for (int p = 0; p < 13; p++) upk2(acc[ri][p], v[2 * p], v[2 * p + 1]);
            float s = 0.f;
            #pragma unroll
            for (int j = 0; j < E_N; j++) {
                float d = selu_f(v[j]);
                v[j] = d;
                s += fabsf(d);
            }
            float inv = __fdividef(1.0f, fmaxf(s, 1e-12f));
            float* ob = out + (size_t)(row0 + tx + 32 * ri) * (HG * E_N)
                            + band * (BAND_HG * E_N) + my * E_N;
            #pragma unroll
            for (int j = 0; j < E_N; j++) ob[j] = v[j] * inv;
        }
        row0 += 64;
    }
}

// ---------------------------------------------------------------------------
extern "C" void kernel_launch(void* const* d_in, const int* in_sizes, int n_in,
                              void* d_out, int out_size) {
    const float* X     = (const float*)d_in[0];
    const float* W1    = (const float*)d_in[1];
    const float* b1    = (const float*)d_in[2];
    const float* W2    = (const float*)d_in[3];
    const float* b2    = (const float*)d_in[4];
    const float* gamma = (const float*)d_in[5];
    const float* beta  = (const float*)d_in[6];
    const float* Wh    = (const float*)d_in[7];
    const float* bh    = (const float*)d_in[8];
    float* out = (float*)d_out;

    cudaFuncSetAttribute(kernA, cudaFuncAttributeMaxDynamicSharedMemorySize, 25856);
    cudaFuncSetAttribute(kernC, cudaFuncAttributeMaxDynamicSharedMemorySize, 46464);

    kernA<<<1024, 128, 25856>>>(X, W1, b1, W2, b2);
    kernB<<<1, 256>>>(gamma, beta);
    kernC<<<dim3(NBAND, 64), 256, 46464>>>(Wh, bh, out);
}

// round 5
// speedup vs baseline: 2.6948x; 2.6948x over previous
#include <cuda_runtime.h>

#define B_N   32768
#define FIN   64
#define HID   32
#define E_N   25
#define HG    96
#define BAND_HG 8
#define NBAND 12
#define MB    224      // 8 heads * 28 (25 padded to 28: f32x2 pairs + 16B-aligned head base)
#define EPD_STRIDE 65  // u64 row stride for e-tile
#define NT    8        // row-tiles per kernC block

typedef unsigned long long u64;

// scratch (static device globals — no allocation)
__device__ float g_h2[B_N * HID];          // 4 MB intermediate
__device__ float g_part[1024][2 * HID];    // per-block BN partial sums
__device__ float g_scale[HID];
__device__ float g_shift[HID];

__device__ __forceinline__ float selu_f(float x) {
    float p = 1.0507009873554805f * x;
    float n = 1.7580993408473766f * (__expf(x) - 1.0f);  // lambda*alpha
    return x > 0.0f ? p : n;
}
__device__ __forceinline__ u64 pk2(float lo, float hi) {
    u64 r;
    asm("mov.b64 %0, {%1,%2};" : "=l"(r)
        : "r"(__float_as_uint(lo)), "r"(__float_as_uint(hi)));
    return r;
}
__device__ __forceinline__ void upk2(u64 v, float& lo, float& hi) {
    unsigned int a, b;
    asm("mov.b64 {%0,%1}, %2;" : "=r"(a), "=r"(b) : "l"(v));
    lo = __uint_as_float(a); hi = __uint_as_float(b);
}
// packed fp32x2 FMA (FFMA2) — only reachable via PTX
#define FFMA2(d, a, b) asm("fma.rn.f32x2 %0, %1, %2, %0;" : "+l"(d) : "l"(a), "l"(b))

// ---------------------------------------------------------------------------
// Kernel A: h = selu(X@W1+b1); h2 = h@W2+b2; store h2 + deterministic BN partials
// grid 1024 x 128 threads; 32 rows/block; 4 threads per row (8 outputs each)
// ---------------------------------------------------------------------------
__global__ void __launch_bounds__(128, 8) kernA(
    const float* __restrict__ X,
    const float* __restrict__ W1, const float* __restrict__ b1,
    const float* __restrict__ W2, const float* __restrict__ b2)
{
    extern __shared__ char sm[];
    float* xs  = (float*)sm;                          // 32*68*4 = 8704 B
    float* w1s = (float*)(sm + 8704);                 // 8192 B
    float* w2s = (float*)(sm + 8704 + 8192);          // 4096 B
    float* b1s = (float*)(sm + 8704 + 8192 + 4096);   // 128 B
    float* b2s = b1s + HID;                           // 128 B
    float* hs  = (float*)(sm + 8704 + 8192 + 4096 + 256); // 32*36*4 = 4608 B

    int t = threadIdx.x;
    int rowbase = blockIdx.x * 32;
    const float* Xb = X + (size_t)rowbase * FIN;

    #pragma unroll
    for (int j = 0; j < 4; j++) {
        int idx = t + j * 128;
        float4 v = ((const float4*)Xb)[idx];
        int row = idx >> 4, col = (idx & 15) * 4;
        *(float4*)&xs[row * 68 + col] = v;
    }
    #pragma unroll
    for (int j = 0; j < 4; j++) ((float4*)w1s)[t + j * 128] = ((const float4*)W1)[t + j * 128];
    #pragma unroll
    for (int j = 0; j < 2; j++) ((float4*)w2s)[t + j * 128] = ((const float4*)W2)[t + j * 128];
    if (t < HID) { b1s[t] = b1[t]; b2s[t] = b2[t]; }
    __syncthreads();

    int r  = t >> 2;        // row 0..31
    int j0 = (t & 3) * 8;   // output col group

    u64 acc[4];
    #pragma unroll
    for (int p = 0; p < 4; p++) acc[p] = *(const u64*)&b1s[j0 + 2 * p];
    #pragma unroll 8
    for (int k = 0; k < FIN; k++) {
        float xk = xs[r * 68 + k];
        u64 xv = pk2(xk, xk);
        ulonglong2 w0 = *(const ulonglong2*)&w1s[k * HID + j0];
        ulonglong2 w1v = *(const ulonglong2*)&w1s[k * HID + j0 + 4];
        FFMA2(acc[0], xv, w0.x);
        FFMA2(acc[1], xv, w0.y);
        FFMA2(acc[2], xv, w1v.x);
        FFMA2(acc[3], xv, w1v.y);
    }
    float hv[8];
    #pragma unroll
    for (int p = 0; p < 4; p++) {
        float a, b; upk2(acc[p], a, b);
        hv[2 * p] = selu_f(a); hv[2 * p + 1] = selu_f(b);
    }
    *(float4*)&hs[r * 36 + j0]     = make_float4(hv[0], hv[1], hv[2], hv[3]);
    *(float4*)&hs[r * 36 + j0 + 4] = make_float4(hv[4], hv[5], hv[6], hv[7]);
    __syncthreads();

    u64 acc2[4];
    #pragma unroll
    for (int p = 0; p < 4; p++) acc2[p] = *(const u64*)&b2s[j0 + 2 * p];
    #pragma unroll 8
    for (int k = 0; k < HID; k++) {
        float hk = hs[r * 36 + k];
        u64 hvv = pk2(hk, hk);
        ulonglong2 w0 = *(const ulonglong2*)&w2s[k * HID + j0];
        ulonglong2 w1v = *(const ulonglong2*)&w2s[k * HID + j0 + 4];
        FFMA2(acc2[0], hvv, w0.x);
        FFMA2(acc2[1], hvv, w0.y);
        FFMA2(acc2[2], hvv, w1v.x);
        FFMA2(acc2[3], hvv, w1v.y);
    }
    float o[8];
    #pragma unroll
    for (int p = 0; p < 4; p++) upk2(acc2[p], o[2 * p], o[2 * p + 1]);

    float* H2r = g_h2 + (size_t)(rowbase + r) * HID + j0;
    *(float4*)H2r       = make_float4(o[0], o[1], o[2], o[3]);
    *(float4*)(H2r + 4) = make_float4(o[4], o[5], o[6], o[7]);

    __syncthreads();
    *(float4*)&hs[r * 36 + j0]     = make_float4(o[0], o[1], o[2], o[3]);
    *(float4*)&hs[r * 36 + j0 + 4] = make_float4(o[4], o[5], o[6], o[7]);
    __syncthreads();

    if (t < HID) {
        float s = 0.f, s2 = 0.f;
        #pragma unroll 8
        for (int rr = 0; rr < 32; rr++) {
            float v = hs[rr * 36 + t];
            s += v; s2 += v * v;
        }
        g_part[blockIdx.x][t]       = s;
        g_part[blockIdx.x][HID + t] = s2;
    }
}

// ---------------------------------------------------------------------------
// Kernel B: fold 1024 partials -> scale/shift (deterministic)
// ---------------------------------------------------------------------------
__global__ void kernB(const float* __restrict__ gamma, const float* __restrict__ beta) {
    __shared__ float ps[8][64];
    int t = threadIdx.x;
    int c = t & 31, ch = t >> 5;
    float s = 0.f, s2 = 0.f;
    #pragma unroll 4
    for (int b = ch * 128; b < ch * 128 + 128; b++) {
        s  += g_part[b][c];
        s2 += g_part[b][HID + c];
    }
    ps[ch][c] = s; ps[ch][HID + c] = s2;
    __syncthreads();
    if (t < HID) {
        float S = 0.f, S2 = 0.f;
        #pragma unroll
        for (int ch2 = 0; ch2 < 8; ch2++) { S += ps[ch2][t]; S2 += ps[ch2][HID + t]; }
        float mu  = S  * (1.0f / B_N);
        float var = S2 * (1.0f / B_N) - mu * mu;
        float sc  = gamma[t] * rsqrtf(var + 1e-5f);
        g_scale[t] = sc;
        g_shift[t] = beta[t] - mu * sc;
    }
}

// ---------------------------------------------------------------------------
// Kernel C: e = selu(BN(h2)); D = e @ Wh (+bh in acc init); selu; L1-norm;
// smem-staged transposed epilogue -> coalesced float4 global stores.
// grid (12 bands, 64) x 256 threads; NT=8 tiles of 64 rows per block.
// smem: bhs[224] | wch[32][224] | sss[64] | epd[32][65] u64 | stg[200][33]
// thread: 2 rows x 13 m-pairs (one head) -> 26 f32x2 accumulators
// ---------------------------------------------------------------------------
__global__ void __launch_bounds__(256, 2) kernC(
    const float* __restrict__ Wh, const float* __restrict__ bh,
    float* __restrict__ out)
{
    extern __shared__ char sm[];
    float* bhs = (float*)sm;                               // 896 B
    float* wch = (float*)(sm + 896);                       // 28672 B
    float* sss = (float*)(sm + 896 + 28672);               // 256 B
    u64*   epd = (u64*)(sm + 896 + 28672 + 256);           // 16640 B
    float* stg = (float*)(sm + 896 + 28672 + 256 + 16640); // 200*33*4 = 26400 B

    int t = threadIdx.x;
    int band = blockIdx.x;

    // biases (pad cols -> 0)
    for (int i = t; i < BAND_HG * 28; i += 256) {
        int hgl = i / 28, j = i - hgl * 28;
        bhs[i] = (j < E_N) ? bh[(band * BAND_HG + hgl) * E_N + j] : 0.0f;
    }
    // weights: Wh[hg][k][j] -> wch[k][hgl*28 + j]; zero pad col 25
    for (int i = t; i < BAND_HG * HID * E_N; i += 256) {
        int hgl = i / (HID * E_N);
        int rem = i - hgl * HID * E_N;
        int k = rem / E_N, j = rem - k * E_N;
        wch[k * MB + hgl * 28 + j] = Wh[(size_t)(band * BAND_HG + hgl) * HID * E_N + rem];
    }
    if (t < HID * BAND_HG) {
        int k = t >> 3, hgl = t & 7;
        wch[k * MB + hgl * 28 + 25] = 0.0f;
    }
    if (t < HID) { sss[t] = g_scale[t]; sss[HID + t] = g_shift[t]; }

    int tx = t & 31;        // row lane
    int my = t >> 5;        // head within band (warp-uniform)
    int wb = my * 28;
    int r8 = t >> 2;        // e-tile row for this thread's 8 h2 elements
    int k0 = (t & 3) * 8;   // e-tile k-group

    int row0 = blockIdx.y * (NT * 64);
    const float* h2p = g_h2 + (size_t)row0 * HID;
    float4 pf0 = ((const float4*)h2p)[t * 2];
    float4 pf1 = ((const float4*)h2p)[t * 2 + 1];

    for (int tile = 0; tile < NT; tile++) {
        __syncthreads();   // weights/sss ready (tile 0) / prev-tile epd+stg reads done
        // epd store: BN + selu, duplicated f32x2, layout [k][row]
        {
            float vv[8] = {pf0.x, pf0.y, pf0.z, pf0.w, pf1.x, pf1.y, pf1.z, pf1.w};
            #pragma unroll
            for (int u = 0; u < 8; u++) {
                float v = fmaf(vv[u], sss[k0 + u], sss[HID + k0 + u]);
                v = selu_f(v);
                epd[(k0 + u) * EPD_STRIDE + r8] = pk2(v, v);
            }
        }
        __syncthreads();

        // prefetch next tile into registers (hidden behind mainloop)
        if (tile < NT - 1) {
            const float* nxt = g_h2 + (size_t)(row0 + 64) * HID;
            pf0 = ((const float4*)nxt)[t * 2];
            pf1 = ((const float4*)nxt)[t * 2 + 1];
        }

        // mainloop; acc init = bias
        u64 acc[2][13];
        #pragma unroll
        for (int p = 0; p < 13; p++) {
            u64 bp = *(const u64*)&bhs[wb + 2 * p];
            acc[0][p] = bp; acc[1][p] = bp;
        }
        #pragma unroll 4
        for (int k = 0; k < HID; k++) {
            u64 e0 = epd[k * EPD_STRIDE + tx];
            u64 e1 = epd[k * EPD_STRIDE + tx + 32];
            const float* wr = &wch[k * MB + wb];
            ulonglong2 wA = *(const ulonglong2*)(wr);
            ulonglong2 wB = *(const ulonglong2*)(wr + 4);
            ulonglong2 wC = *(const ulonglong2*)(wr + 8);
            ulonglong2 wD = *(const ulonglong2*)(wr + 12);
            ulonglong2 wE = *(const ulonglong2*)(wr + 16);
            ulonglong2 wF = *(const ulonglong2*)(wr + 20);
            u64 wG = *(const u64*)(wr + 24);
            FFMA2(acc[0][0], e0, wA.x);  FFMA2(acc[1][0], e1, wA.x);
            FFMA2(acc[0][1], e0, wA.y);  FFMA2(acc[1][1], e1, wA.y);
            FFMA2(acc[0][2], e0, wB.x);  FFMA2(acc[1][2], e1, wB.x);
            FFMA2(acc[0][3], e0, wB.y);  FFMA2(acc[1][3], e1, wB.y);
            FFMA2(acc[0][4], e0, wC.x);  FFMA2(acc[1][4], e1, wC.x);
            FFMA2(acc[0][5], e0, wC.y);  FFMA2(acc[1][5], e1, wC.y);
            FFMA2(acc[0][6], e0, wD.x);  FFMA2(acc[1][6], e1, wD.x);
            FFMA2(acc[0][7], e0, wD.y);  FFMA2(acc[1][7], e1, wD.y);
            FFMA2(acc[0][8], e0, wE.x);  FFMA2(acc[1][8], e1, wE.x);
            FFMA2(acc[0][9], e0, wE.y);  FFMA2(acc[1][9], e1, wE.y);
            FFMA2(acc[0][10], e0, wF.x); FFMA2(acc[1][10], e1, wF.x);
            FFMA2(acc[0][11], e0, wF.y); FFMA2(acc[1][11], e1, wF.y);
            FFMA2(acc[0][12], e0, wG);   FFMA2(acc[1][12], e1, wG);
        }

        // epilogue: two 32-row halves, staged transposed, coalesced STG.128
        #pragma unroll
        for (int ri = 0; ri < 2; ri++) {
            if (ri) __syncthreads();   // tile-top barrier covers ri=0 staging reuse
            {
                float v[26];
                #pragma unroll
                for (int p = 0; p < 13; p++) upk2(acc[ri][p], v[2 * p], v[2 * p + 1]);
                float s = 0.f;
                #pragma unroll
                for (int j = 0; j < E_N; j++) {
                    float d = selu_f(v[j]);
                    v[j] = d;
                    s += fabsf(d);
                }
                float inv = __fdividef(1.0f, fmaxf(s, 1e-12f));
                #pragma unroll
                for (int j = 0; j < E_N; j++)
                    stg[(my * E_N + j) * 33 + tx] = v[j] * inv;  // sign(d)*|d|/l1 == d/l1
            }
            __syncthreads();
            float* ob = out + (size_t)(row0 + 32 * ri) * (HG * E_N) + band * (BAND_HG * E_N);
            for (int i = t; i < 32 * 50; i += 256) {
                int r = i / 50, q = i - r * 50;
                float4 vv;
                vv.x = stg[(4 * q + 0) * 33 + r];
                vv.y = stg[(4 * q + 1) * 33 + r];
                vv.z = stg[(4 * q + 2) * 33 + r];
                vv.w = stg[(4 * q + 3) * 33 + r];
                *(float4*)(ob + (size_t)r * (HG * E_N) + 4 * q) = vv;  // 16B aligned
            }
        }
        row0 += 64;
    }
}

// ---------------------------------------------------------------------------
extern "C" void kernel_launch(void* const* d_in, const int* in_sizes, int n_in,
                              void* d_out, int out_size) {
    const float* X     = (const float*)d_in[0];
    const float* W1    = (const float*)d_in[1];
    const float* b1    = (const float*)d_in[2];
    const float* W2    = (const float*)d_in[3];
    const float* b2    = (const float*)d_in[4];
    const float* gamma = (const float*)d_in[5];
    const float* beta  = (const float*)d_in[6];
    const float* Wh    = (const float*)d_in[7];
    const float* bh    = (const float*)d_in[8];
    float* out = (float*)d_out;

    cudaFuncSetAttribute(kernA, cudaFuncAttributeMaxDynamicSharedMemorySize, 25856);
    cudaFuncSetAttribute(kernC, cudaFuncAttributeMaxDynamicSharedMemorySize, 72864);

    kernA<<<1024, 128, 25856>>>(X, W1, b1, W2, b2);
    kernB<<<1, 256>>>(gamma, beta);
    kernC<<<dim3(NBAND, 64), 256, 72864>>>(Wh, bh, out);
}